// round 8
// baseline (speedup 1.0000x reference)
#include <cuda_runtime.h>

#define B_   64
#define NI   2048
#define NO   32
#define DDO  16
#define DDI  16
#define OD   512
#define NBLK 148
#define THREADS 512

typedef unsigned long long ull;

// ---- shared memory (float offsets) ----
#define WT_PITCH 516
#define WT_SZ    (DDI * WT_PITCH)            // 8256
#define S_WT(b)  ((b) * WT_SZ)               // two W buffers: 0 / 8256
#define S_XD(b)  (16512 + (b) * 2048)        // two x buffers (float4 [8][64])
#define S_WS     20608                       // Wsum [16][33]
#define S_CT(b)  (21136 + (b) * 2176)        // two c2 buffers [32][68]
#define SMEM_FLOATS 25488                    // 101952 B

#define XCOL(b) ((((b) & 3) << 4) | ((b) >> 2))

// partials: [seg][o][b][d] ; monotone grid-sync ticket
__device__ float    g_part[(size_t)NBLK * OD * B_];
__device__ unsigned g_cnt = 0;

__device__ __forceinline__ void fma2(ull& d, ull a, ull b) {
    asm("fma.rn.f32x2 %0, %1, %2, %0;" : "+l"(d) : "l"(a), "l"(b));
}
__device__ __forceinline__ ull mul2(ull a, ull b) {
    ull r; asm("mul.rn.f32x2 %0, %1, %2;" : "=l"(r) : "l"(a), "l"(b)); return r;
}
__device__ __forceinline__ ull pack_dup(float a) {
    ull r; asm("mov.b64 %0, {%1, %1};" : "=l"(r) : "f"(a)); return r;
}
__device__ __forceinline__ ull pack2(float a, float b) {
    ull r; asm("mov.b64 %0, {%1, %2};" : "=l"(r) : "f"(a), "f"(b)); return r;
}
__device__ __forceinline__ float2 unpk(ull a) {
    float2 r; asm("mov.b64 {%0, %1}, %2;" : "=f"(r.x), "=f"(r.y) : "l"(a)); return r;
}

extern "C" __global__ void __launch_bounds__(THREADS, 1)
capsule_main(const float* __restrict__ X, const float* __restrict__ W,
             float* __restrict__ out)
{
    extern __shared__ float sm[];
    float* sWs = sm + S_WS;

    const int tid  = threadIdx.x;
    const int lane = tid & 31;
    const int wid  = tid >> 5;
    const int o    = tid >> 4;
    const int bg   = tid & 15;
    const int b0   = 4 * bg;

    ull acc[8][4];
    #pragma unroll
    for (int p = 0; p < 8; p++)
        #pragma unroll
        for (int j = 0; j < 4; j++) acc[p][j] = 0ull;

    float4 wv[4];
    float4 xv;

    // ---------------- helpers as macros over locals ----------------
#define LDG_TILE(nn)                                                          \
    {                                                                         \
        const float4* Wg = (const float4*)(W + (size_t)(nn) * (OD * DDI));    \
        wv[0] = Wg[tid]; wv[1] = Wg[tid + 512];                               \
        wv[2] = Wg[tid + 1024]; wv[3] = Wg[tid + 1536];                       \
        if (tid < 256)                                                        \
            xv = *(const float4*)(X + ((size_t)(tid >> 2) * NI + (nn)) * DDI  \
                                  + (tid & 3) * 4);                           \
    }

#define STAGE_TILE(bf)                                                        \
    {                                                                         \
        float* wt = sm + S_WT(bf);                                            \
        _Pragma("unroll")                                                     \
        for (int k = 0; k < 4; k++) {                                         \
            int g = tid + k * THREADS;                                        \
            int od = g >> 2, i0 = (g & 3) * 4;                                \
            wt[(i0 + 0) * WT_PITCH + od] = wv[k].x;                           \
            wt[(i0 + 1) * WT_PITCH + od] = wv[k].y;                           \
            wt[(i0 + 2) * WT_PITCH + od] = wv[k].z;                           \
            wt[(i0 + 3) * WT_PITCH + od] = wv[k].w;                           \
        }                                                                     \
        if (tid < 256) {                                                      \
            int b = tid >> 2, i0 = (tid & 3) * 4, bc = XCOL(b);               \
            float4* xd = (float4*)(sm + S_XD(bf));                            \
            xd[(i0 >> 1) * 64 + bc]       = make_float4(xv.x, xv.x, xv.y, xv.y); \
            xd[((i0 >> 1) + 1) * 64 + bc] = make_float4(xv.z, xv.z, xv.w, xv.w); \
        }                                                                     \
    }

#define WSUM(bf)                                                              \
    {                                                                         \
        int oo = tid >> 4, ii = tid & 15;                                     \
        const float* r = sm + S_WT(bf) + ii * WT_PITCH + oo * 16;             \
        float4 a = *(const float4*)(r);                                       \
        float4 b = *(const float4*)(r + 4);                                   \
        float4 c = *(const float4*)(r + 8);                                   \
        float4 d = *(const float4*)(r + 12);                                  \
        sWs[ii * 33 + oo] =                                                   \
            ((a.x + a.y) + (a.z + a.w)) + ((b.x + b.y) + (b.z + b.w)) +       \
            ((c.x + c.y) + (c.z + c.w)) + ((d.x + d.y) + (d.z + d.w));        \
    }

#define ROUTE(bf)                                                             \
    {                                                                         \
        const float* xd = sm + S_XD(bf);                                      \
        float* ct = sm + S_CT(bf);                                            \
        _Pragma("unroll")                                                     \
        for (int bb = 0; bb < 4; bb++) {                                      \
            int b = wid + 16 * bb;                                            \
            int bc4 = 4 * XCOL(b);                                            \
            float h = 0.f;                                                    \
            _Pragma("unroll")                                                 \
            for (int i = 0; i < DDI; i++)                                     \
                h = fmaf(sWs[i * 33 + lane],                                  \
                         xd[(i >> 1) * 256 + bc4 + 2 * (i & 1)], h);          \
            float b1 = h * 0.03125f;                                          \
            float e1 = __expf(b1);                                            \
            float s1 = e1;                                                    \
            _Pragma("unroll")                                                 \
            for (int off = 16; off; off >>= 1)                                \
                s1 += __shfl_xor_sync(0xffffffffu, s1, off);                  \
            float b2 = fmaf(__fdividef(e1, s1), h, b1);                       \
            float e2 = __expf(b2);                                            \
            float s2 = e2;                                                    \
            _Pragma("unroll")                                                 \
            for (int off = 16; off; off >>= 1)                                \
                s2 += __shfl_xor_sync(0xffffffffu, s2, off);                  \
            ct[lane * 68 + b] = __fdividef(e2, s2);                           \
        }                                                                     \
    }

    // ---------------- prologue: stage + route n0, prefetch n1 ----------------
    int n = blockIdx.x;
    LDG_TILE(n);
    STAGE_TILE(0);
    __syncthreads();
    WSUM(0);
    if (n + NBLK < NI) LDG_TILE(n + NBLK);
    __syncthreads();
    ROUTE(0);

    int buf = 0;
    for (; n < NI; n += NBLK) {
        __syncthreads();                                   // A: prior readers done
        const bool hn = (n + NBLK) < NI;
        if (hn) STAGE_TILE(buf ^ 1);
        __syncthreads();                                   // B: staged visible
        if (hn) {
            WSUM(buf ^ 1);
            if (n + 2 * NBLK < NI) LDG_TILE(n + 2 * NBLK);
        }
        __syncthreads();                                   // C: Ws visible

        if (hn) ROUTE(buf ^ 1);                            // overlaps contraction below

        // ---- contraction for n (buffer `buf`) ----
        {
            const float*  wt  = sm + S_WT(buf);
            const float4* xd4 = (const float4*)(sm + S_XD(buf));
            float4 cv = *(const float4*)(sm + S_CT(buf) + o * 68 + b0);
            ull c2d[4];
            c2d[0] = pack_dup(cv.x); c2d[1] = pack_dup(cv.y);
            c2d[2] = pack_dup(cv.z); c2d[3] = pack_dup(cv.w);

            #pragma unroll
            for (int i2 = 0; i2 < 8; i2++) {
                ull xsA[4], xsB[4];
                #pragma unroll
                for (int j = 0; j < 4; j++) {
                    float4 xj = xd4[i2 * 64 + j * 16 + bg];
                    xsA[j] = mul2(pack2(xj.x, xj.y), c2d[j]);
                    xsB[j] = mul2(pack2(xj.z, xj.w), c2d[j]);
                }
                const float* ra = wt + (2 * i2) * WT_PITCH + o * 16;
                const float* rb = ra + WT_PITCH;
                #pragma unroll
                for (int jj = 0; jj < 4; jj++) {
                    ulonglong2 wa = *(const ulonglong2*)(ra + 4 * jj);
                    ulonglong2 wb = *(const ulonglong2*)(rb + 4 * jj);
                    #pragma unroll
                    for (int j = 0; j < 4; j++) {
                        fma2(acc[2 * jj + 0][j], wa.x, xsA[j]);
                        fma2(acc[2 * jj + 1][j], wa.y, xsA[j]);
                        fma2(acc[2 * jj + 0][j], wb.x, xsB[j]);
                        fma2(acc[2 * jj + 1][j], wb.y, xsB[j]);
                    }
                }
            }
        }
        buf ^= 1;
    }

    // ---- writeout partials: g_part[seg][o][b][d] ----
    float* gp = g_part + (size_t)blockIdx.x * (OD * B_) + o * 1024 + b0 * 16;
    #pragma unroll
    for (int j = 0; j < 4; j++) {
        #pragma unroll
        for (int q = 0; q < 4; q++) {
            float2 a0 = unpk(acc[2 * q + 0][j]);
            float2 a1 = unpk(acc[2 * q + 1][j]);
            *(float4*)(gp + j * 16 + 4 * q) = make_float4(a0.x, a0.y, a1.x, a1.y);
        }
    }

    // ---- software grid barrier (monotone ticket; graph-replay safe) ----
    __threadfence();
    __syncthreads();
    if (tid == 0) {
        unsigned t = atomicAdd(&g_cnt, 1u);
        unsigned target = (t / NBLK + 1u) * NBLK;
        while ((int)(*(volatile unsigned*)&g_cnt) - (int)target < 0) {}
        __threadfence();
    }
    __syncthreads();

    // ---- fused reduce + squash: 4 threads per float2-output, 37 segs each ----
    {
        const int g = blockIdx.x * THREADS + tid;
        if (g < 65536) {
            const int e    = g >> 2;
            const int part = g & 3;

            const float2* p = ((const float2*)g_part) + (size_t)part * 16384 + e;
            float sx = 0.f, sy = 0.f;
            #pragma unroll
            for (int k = 0; k < 37; k++) {
                const float2* q = p + (size_t)(4 * k) * 16384;
                float2 v;
                v.x = __ldcg(&q->x); v.y = __ldcg(&q->y);
                sx += v.x; sy += v.y;
            }
            sx += __shfl_xor_sync(0xffffffffu, sx, 1);
            sx += __shfl_xor_sync(0xffffffffu, sx, 2);
            sy += __shfl_xor_sync(0xffffffffu, sy, 1);
            sy += __shfl_xor_sync(0xffffffffu, sy, 2);

            float qv = sx * sx + sy * sy;
            qv += __shfl_xor_sync(0xffffffffu, qv, 4);
            qv += __shfl_xor_sync(0xffffffffu, qv, 8);
            qv += __shfl_xor_sync(0xffffffffu, qv, 16);
            float s2 = qv;

            if (part == 0) {
                float scale = s2 / ((1.f + s2) * sqrtf(s2 + 1e-7f));
                int oo = e >> 9, bb = (e >> 3) & 63, dp = e & 7;
                *(float2*)(out + (size_t)bb * (NO * DDO) + oo * 16 + 2 * dp) =
                    make_float2(scale * sx, scale * sy);
            }
        }
    }
}

extern "C" void kernel_launch(void* const* d_in, const int* in_sizes, int n_in,
                              void* d_out, int out_size)
{
    const float* a = (const float*)d_in[0];
    const float* c = (const float*)d_in[1];
    const float *X, *W;
    if (in_sizes[0] == B_ * NI * DDI) { X = a; W = c; }
    else                              { X = c; W = a; }

    size_t smem = (size_t)SMEM_FLOATS * sizeof(float);
    cudaFuncSetAttribute(capsule_main,
                         cudaFuncAttributeMaxDynamicSharedMemorySize, (int)smem);
    capsule_main<<<NBLK, THREADS, smem>>>(X, W, (float*)d_out);
}